// round 14
// baseline (speedup 1.0000x reference)
#include <cuda_runtime.h>
#include <cuda_bf16.h>
#include <cstdint>

#define B_   4
#define N_   40
#define NC   64000      // 40^3
#define RT   256000     // B * N^3
#define WST  136

typedef unsigned long long u64;

// ---------------- scratch (device globals per allocation rules) ------------
__device__ float g_xembed[(size_t)RT * 128];
__device__ float g_sumexp[B_ * 128];
__device__ int   g_len[B_];
__device__ __align__(16) unsigned short g_wT[4][128 * WST];     // Wi1/Wi2 hi,lo [n][k]
__device__ __align__(16) unsigned short g_weT[2][128 * WST];    // We hi,lo [n][k]
__device__ __align__(16) unsigned short g_wo1T[2][256 * 256];   // Wo1 hi,lo [n][k]

// ---------------- helpers ---------------------------------------------------
static __device__ __forceinline__ uint32_t smem_u32(const void* p) {
    uint32_t a;
    asm("{ .reg .u64 t; cvta.to.shared.u64 t, %1; cvt.u32.u64 %0, t; }" : "=r"(a) : "l"(p));
    return a;
}
static __device__ __forceinline__ float bfhi(float f) {
    return __bfloat162float(__float2bfloat16(f));
}
static __device__ __forceinline__ uint32_t pack_bf2(float lo, float hi) {
    __nv_bfloat162 h = __floats2bfloat162_rn(lo, hi);
    return *reinterpret_cast<uint32_t*>(&h);
}
static __device__ __forceinline__ void ldsm_x4(uint32_t a, uint32_t* r) {
    asm volatile("ldmatrix.sync.aligned.m8n8.x4.shared.b16 {%0,%1,%2,%3}, [%4];"
        : "=r"(r[0]), "=r"(r[1]), "=r"(r[2]), "=r"(r[3]) : "r"(a));
}
static __device__ __forceinline__ void mma16816(float* d, const uint32_t* a, const uint32_t* b) {
    asm volatile("mma.sync.aligned.m16n8k16.row.col.f32.bf16.bf16.f32 "
        "{%0,%1,%2,%3}, {%4,%5,%6,%7}, {%8,%9}, {%0,%1,%2,%3};"
        : "+f"(d[0]), "+f"(d[1]), "+f"(d[2]), "+f"(d[3])
        : "r"(a[0]), "r"(a[1]), "r"(a[2]), "r"(a[3]), "r"(b[0]), "r"(b[1]));
}

// ---------------------------------------------------------------------------
// Kernel 0a: mask -> lengths, zero softmax denominators.
// ---------------------------------------------------------------------------
__global__ void k_setup(const unsigned char* __restrict__ mraw) {
    int t = threadIdx.x;
    if (t < B_ * 128) g_sumexp[t] = 0.f;
    if (t < B_) {
        int cnt = 0;
        if (mraw[1] != 0) {
            for (int j = 0; j < N_; j++) cnt += (mraw[t * N_ + j] != 0) ? 1 : 0;
        } else {
            const unsigned int* mi = (const unsigned int*)mraw;
            for (int j = 0; j < N_; j++) cnt += (mi[t * N_ + j] != 0u) ? 1 : 0;
        }
        g_len[t] = cnt;
    }
}

// ---------------------------------------------------------------------------
// Kernel 0b: transposed bf16 hi/lo weight images for Wi1, Wi2, We, Wo1.
// ---------------------------------------------------------------------------
__global__ void k_prep(const float* __restrict__ Wi1, const float* __restrict__ Wi2,
                       const float* __restrict__ We,  const float* __restrict__ Wo1) {
    int idx = blockIdx.x * 256 + threadIdx.x;
    if (idx < 4 * 128 * WST) {
        int mat = idx / (128 * WST);
        int r   = idx % (128 * WST);
        int n   = r / WST;
        int k   = r % WST;
        float v = 0.f;
        if (k < 128) {
            v = (mat < 2 ? Wi1 : Wi2)[k * 128 + n];
            if (mat & 1) v = v - bfhi(v);
        }
        __nv_bfloat16 h = __float2bfloat16(v);
        g_wT[mat][n * WST + k] = *reinterpret_cast<unsigned short*>(&h);
    } else if (idx < 6 * 128 * WST) {
        int r   = idx - 4 * 128 * WST;
        int img = r / (128 * WST);
        int rr  = r % (128 * WST);
        int n   = rr / WST;
        int k   = rr % WST;
        float v = 0.f;
        if (k < 128) {
            v = We[k * 128 + n];
            if (img) v = v - bfhi(v);
        }
        __nv_bfloat16 h = __float2bfloat16(v);
        g_weT[img][n * WST + k] = *reinterpret_cast<unsigned short*>(&h);
    } else if (idx < 6 * 128 * WST + 2 * 65536) {
        int r   = idx - 6 * 128 * WST;
        int img = r / 65536;
        int rr  = r % 65536;
        int n   = rr / 256;
        int k   = rr % 256;
        float v = Wo1[k * 256 + n];
        if (img) v = v - bfhi(v);
        __nv_bfloat16 h = __float2bfloat16(v);
        g_wo1T[img][n * 256 + k] = *reinterpret_cast<unsigned short*>(&h);
    }
}

// ---------------------------------------------------------------------------
// Kernel 1 (HMMA v2): 256 rows per CTA as two sequential 128-row tiles;
// weight images staged ONCE per CTA (halves weight L2 traffic).
// ---------------------------------------------------------------------------
#define AHI_OFF 0
#define ALO_OFF 34816
#define W_OFF   69632
#define WIMG    34816
#define SXF_STRIDE 132
#define DSMEM   208896

extern __shared__ unsigned char sdyn[];
__global__ __launch_bounds__(256, 1) void k_embed_hmma(
    const float* __restrict__ x,
    const float* __restrict__ bi1, const float* __restrict__ bi2)
{
    __shared__ float s_bias1[128], s_bias2[128];
    __shared__ unsigned char s_vf[256];

    const int t    = threadIdx.x;
    const int lane = t & 31;
    const int w    = t >> 5;
    const int row0 = blockIdx.x * 256;    // 64000 % 256 == 0: no batch straddle
    const int b    = row0 / NC;
    const uint32_t sbase = smem_u32(sdyn);

    // weight images -> smem ONCE (139264 B)
    {
        const float4* ws = (const float4*)g_wT;
        float4* wd = (float4*)(sdyn + W_OFF);
        #pragma unroll
        for (int i = 0; i < 34; i++) wd[t + i * 256] = ws[t + i * 256];
    }
    if (t < 128) {
        s_bias1[t] = bi1[t];
        s_bias2[t] = bi2[t];
    }
    {
        const int lenb = g_len[b];
        const int rem = row0 + t - b * NC;
        const int i  = rem / 1600;
        const int j  = (rem / 40) % 40;
        const int kk = rem % 40;
        s_vf[t] = (i < j) && (j < kk) && (kk < lenb);
    }

    const int m0 = w * 16;
    const int c2 = (lane & 3) * 2;
    const int g  = lane >> 2;
    const uint32_t aHi = sbase + AHI_OFF + (((m0 + (lane & 15)) * WST + (lane >> 4) * 8) << 1);
    const uint32_t aLo = aHi + (ALO_OFF - AHI_OFF);
    const uint32_t bPr = sbase + W_OFF +
        (((((lane & 7) + ((lane >> 4) << 3)) * WST) + ((lane >> 3) & 1) * 8) << 1);

    float es = 0.f;   // per-thread sumexp accumulator (t < 128 = column)

    #pragma unroll 1
    for (int tile = 0; tile < 2; tile++) {
        const int r0g = row0 + tile * 128;

        __syncthreads();   // prior tile's sxf reads (and weight copy) complete
        // load x tile -> bf16 hi/lo A images
        {
            const float4* xg = (const float4*)(x + (size_t)r0g * 128);
            #pragma unroll
            for (int i = 0; i < 16; i++) {
                int fidx = t + i * 256;
                float4 v = xg[fidx];
                int row = fidx >> 5;
                int k   = (fidx & 31) * 4;
                uint32_t hA = pack_bf2(v.x, v.y);
                uint32_t hB = pack_bf2(v.z, v.w);
                uint32_t lA = pack_bf2(v.x - bfhi(v.x), v.y - bfhi(v.y));
                uint32_t lB = pack_bf2(v.z - bfhi(v.z), v.w - bfhi(v.w));
                size_t off = ((size_t)row * WST + k) * 2;
                *(u64*)(sdyn + AHI_OFF + off) = ((u64)hB << 32) | hA;
                *(u64*)(sdyn + ALO_OFF + off) = ((u64)lB << 32) | lA;
            }
        }
        __syncthreads();

        float acc[16][4];
        #pragma unroll
        for (int nt = 0; nt < 16; nt++)
            acc[nt][0] = acc[nt][1] = acc[nt][2] = acc[nt][3] = 0.f;

        // ---- GEMM1: x @ Wi1 (bf16x3) ----
        #pragma unroll
        for (int ks = 0; ks < 8; ks++) {
            uint32_t ahi[4], alo[4];
            ldsm_x4(aHi + ks * 32, ahi);
            ldsm_x4(aLo + ks * 32, alo);
            #pragma unroll
            for (int nt = 0; nt < 16; nt += 2) {
                uint32_t bh[4], bl[4];
                ldsm_x4(bPr + 0 * WIMG + nt * (8 * WST * 2) + ks * 32, bh);
                ldsm_x4(bPr + 1 * WIMG + nt * (8 * WST * 2) + ks * 32, bl);
                mma16816(acc[nt], ahi, bh);     mma16816(acc[nt + 1], ahi, bh + 2);
                mma16816(acc[nt], ahi, bl);     mma16816(acc[nt + 1], ahi, bl + 2);
                mma16816(acc[nt], alo, bh);     mma16816(acc[nt + 1], alo, bh + 2);
            }
        }
        __syncthreads();   // all warps done reading A images (sxf aliases them)

        // ---- epilogue 1 (regs): y1 = relu(acc + bi1) -> A2 fragments ----
        uint32_t a2h[8][4], a2l[8][4];
        #pragma unroll
        for (int ks = 0; ks < 8; ks++) {
            #pragma unroll
            for (int h = 0; h < 2; h++) {
                const int nt = 2 * ks + h;
                const float b0 = s_bias1[nt * 8 + c2];
                const float b1 = s_bias1[nt * 8 + c2 + 1];
                float f0 = fmaxf(acc[nt][0] + b0, 0.f);
                float f1 = fmaxf(acc[nt][1] + b1, 0.f);
                float f2 = fmaxf(acc[nt][2] + b0, 0.f);
                float f3 = fmaxf(acc[nt][3] + b1, 0.f);
                a2h[ks][0 + 2 * h] = pack_bf2(f0, f1);
                a2h[ks][1 + 2 * h] = pack_bf2(f2, f3);
                a2l[ks][0 + 2 * h] = pack_bf2(f0 - bfhi(f0), f1 - bfhi(f1));
                a2l[ks][1 + 2 * h] = pack_bf2(f2 - bfhi(f2), f3 - bfhi(f3));
            }
        }

        // ---- GEMM2: y1 @ Wi2 (bf16x3), A from registers ----
        #pragma unroll
        for (int nt = 0; nt < 16; nt++)
            acc[nt][0] = acc[nt][1] = acc[nt][2] = acc[nt][3] = 0.f;
        #pragma unroll
        for (int ks = 0; ks < 8; ks++) {
            #pragma unroll
            for (int nt = 0; nt < 16; nt += 2) {
                uint32_t bh[4], bl[4];
                ldsm_x4(bPr + 2 * WIMG + nt * (8 * WST * 2) + ks * 32, bh);
                ldsm_x4(bPr + 3 * WIMG + nt * (8 * WST * 2) + ks * 32, bl);
                mma16816(acc[nt], a2h[ks], bh); mma16816(acc[nt + 1], a2h[ks], bh + 2);
                mma16816(acc[nt], a2h[ks], bl); mma16816(acc[nt + 1], a2h[ks], bl + 2);
                mma16816(acc[nt], a2l[ks], bh); mma16816(acc[nt + 1], a2l[ks], bh + 2);
            }
        }

        // ---- epilogue 2: xf = acc + bi2 -> smem (stride 132) ----
        float* sxf = (float*)sdyn;   // aliases dead A images
        #pragma unroll
        for (int nt = 0; nt < 16; nt++) {
            const int nc = nt * 8 + c2;
            const float b0 = s_bias2[nc], b1 = s_bias2[nc + 1];
            *(float2*)(&sxf[(m0 + g) * SXF_STRIDE + nc])     = make_float2(acc[nt][0] + b0, acc[nt][1] + b1);
            *(float2*)(&sxf[(m0 + g + 8) * SXF_STRIDE + nc]) = make_float2(acc[nt][2] + b0, acc[nt][3] + b1);
        }
        __syncthreads();

        // coalesced store of xf
        {
            float4* xo = (float4*)(g_xembed + (size_t)r0g * 128);
            #pragma unroll
            for (int i = 0; i < 16; i++) {
                int idx = t + i * 256;
                int row = idx >> 5;
                int c4  = (idx & 31) * 4;
                const float* p = &sxf[row * SXF_STRIDE + c4];
                xo[idx] = make_float4(p[0], p[1], p[2], p[3]);
            }
        }
        // per-column sumexp over valid rows of this tile
        if (t < 128) {
            const unsigned char* vf = &s_vf[tile * 128];
            for (int r = 0; r < 128; r++)
                if (vf[r]) es += __expf(sxf[r * SXF_STRIDE + t]);
        }
    }
    if (t < 128 && es != 0.f) atomicAdd(&g_sumexp[b * 128 + t], es);
}

// ---------------------------------------------------------------------------
// Kernel 2 (HMMA v4.1): 256 rows per CTA, warp = M32 (two m-tiles).
// Stage A processes m-tiles SEQUENTIALLY (one acc[4][4] live) to stay under
// the register spill cliff. Stage B: Wo1 in 64-col quarters shared by both
// m-tiles (per-row B traffic halved).
// ---------------------------------------------------------------------------
#define XFHI 0
#define XFLO 69632
#define WEHI 139264
#define WQHI 139264
#define WQLO 173056
#define DSMEM_OUT 206848

// copy one 64-col Wo1 quarter image into a 264-stride smem buffer.
static __device__ __forceinline__ void copy_wo1_quarter(
    unsigned char* sm, uint32_t dst0, int img, int q, int t, bool full)
{
    const uint4* src = (const uint4*)(g_wo1T[img] + (size_t)(q * 64) * 256);
    if (full) {
        #pragma unroll
        for (int i = 0; i < 8; i++) {
            int e = t + i * 256;
            int r = e >> 5;
            int kq = (e & 31) * 8;
            *(uint4*)(sm + dst0 + ((r * 264 + kq) << 1)) = src[e];
        }
    } else {
        #pragma unroll
        for (int i = 0; i < 4; i++) {
            int e = t + i * 256;
            int r = e >> 4;
            int kq = 128 + (e & 15) * 8;
            *(uint4*)(sm + dst0 + ((r * 264 + kq) << 1)) = src[r * 32 + (kq >> 3)];
        }
    }
}

__global__ __launch_bounds__(256, 1) void k_out_hmma(
    const float* __restrict__ bo1,
    const float* __restrict__ Wo2, const float* __restrict__ bo2,
    float* __restrict__ out)
{
    __shared__ float s_bo1[256], s_wo2[256], s_inv[128];
    __shared__ unsigned char s_vf[256];

    const int t    = threadIdx.x;
    const int lane = t & 31;
    const int w    = t >> 5;
    const int row0 = blockIdx.x * 256;
    const int b    = row0 / NC;
    const uint32_t sbase = smem_u32(sdyn);

    if (t < 128) s_inv[t] = 1.0f / g_sumexp[b * 128 + t];
    {
        const int lenb = g_len[b];
        const int rem = row0 + t - b * NC;
        const int i  = rem / 1600;
        const int j  = (rem / 40) % 40;
        const int kk = rem % 40;
        s_vf[t] = (i < j) && (j < kk) && (kk < lenb);
    }
    s_bo1[t] = bo1[t];
    s_wo2[t] = Wo2[t];
    const int bany = __syncthreads_or((int)s_vf[t]);

    // xf tiles (256 rows) -> bf16 hi/lo images
    {
        const float4* xg = (const float4*)(g_xembed + (size_t)row0 * 128);
        #pragma unroll
        for (int i = 0; i < 32; i++) {
            int fidx = t + i * 256;
            float4 v = xg[fidx];
            int row = fidx >> 5;
            int k   = (fidx & 31) * 4;
            uint32_t hA = pack_bf2(v.x, v.y);
            uint32_t hB = pack_bf2(v.z, v.w);
            uint32_t lA = pack_bf2(v.x - bfhi(v.x), v.y - bfhi(v.y));
            uint32_t lB = pack_bf2(v.z - bfhi(v.z), v.w - bfhi(v.w));
            size_t off = ((size_t)row * WST + k) * 2;
            *(u64*)(sdyn + XFHI + off) = ((u64)hB << 32) | hA;
            *(u64*)(sdyn + XFLO + off) = ((u64)lB << 32) | lA;
        }
    }
    // We hi image (stage A plain bf16) — only when CTA has valid rows
    if (bany) {
        const float4* ws = (const float4*)g_weT[0];
        float4* wd = (float4*)(sdyn + WEHI);
        #pragma unroll
        for (int i = 0; i < 9; i++) {
            int e = t + i * 256;
            if (e < 2176) wd[e] = ws[e];
        }
    }
    __syncthreads();

    const int c2 = (lane & 3) * 2;
    const int g  = lane >> 2;
    const uint32_t aAddr0 = sbase + XFHI + (((w * 16 + (lane & 15)) * WST + (lane >> 4) * 8) << 1);
    const uint32_t aAddr1 = aAddr0 + (128 * WST * 2);
    const uint32_t bPr136 = sbase +
        (((((lane & 7) + ((lane >> 4) << 3)) * WST) + ((lane >> 3) & 1) * 8) << 1);

    const int anyv0 = __any_sync(0xffffffffu, (int)s_vf[w * 16 + (lane & 15)]);
    const int anyv1 = __any_sync(0xffffffffu, (int)s_vf[128 + w * 16 + (lane & 15)]);

    // ---- stage A (plain bf16): axi = a .* relu(xf @ We) — m-tiles SEQUENTIAL ----
    uint32_t axh[2][8][4];
    #pragma unroll
    for (int mt = 0; mt < 2; mt++) {
        if (!(mt == 0 ? anyv0 : anyv1)) continue;
        const uint32_t aA = (mt == 0) ? aAddr0 : aAddr1;
        const int r0 = mt * 128 + w * 16 + g, r1 = r0 + 8;
        const bool v0 = s_vf[r0], v1 = s_vf[r1];
        #pragma unroll
        for (int ntg = 0; ntg < 16; ntg += 4) {
            float acc[4][4];
            #pragma unroll
            for (int q = 0; q < 4; q++)
                acc[q][0] = acc[q][1] = acc[q][2] = acc[q][3] = 0.f;
            #pragma unroll
            for (int ks = 0; ks < 8; ks++) {
                uint32_t ah[4];
                ldsm_x4(aA + ks * 32, ah);
                uint32_t bhA[4], bhB[4];
                ldsm_x4(bPr136 + WEHI + (ntg + 0) * (8 * WST * 2) + ks * 32, bhA);
                ldsm_x4(bPr136 + WEHI + (ntg + 2) * (8 * WST * 2) + ks * 32, bhB);
                mma16816(acc[0], ah, bhA);  mma16816(acc[1], ah, bhA + 2);
                mma16816(acc[2], ah, bhB);  mma16816(acc[3], ah, bhB + 2);
            }
            #pragma unroll
            for (int q = 0; q < 4; q++) {
                const int nt = ntg + q;
                const int c = nt * 8 + c2;
                const float i0 = s_inv[c], i1 = s_inv[c + 1];
                float v00 = 0.f, v01 = 0.f, v10 = 0.f, v11 = 0.f;
                if (v0) {
                    __nv_bfloat162 h = *(__nv_bfloat162*)(sdyn + XFHI + ((r0 * WST + c) << 1));
                    __nv_bfloat162 l = *(__nv_bfloat162*)(sdyn + XFLO + ((r0 * WST + c) << 1));
                    float x0 = __bfloat162float(h.x) + __bfloat162float(l.x);
                    float x1 = __bfloat162float(h.y) + __bfloat162float(l.y);
                    v00 = __expf(x0) * i0 * fmaxf(acc[q][0], 0.f);
                    v01 = __expf(x1) * i1 * fmaxf(acc[q][1], 0.f);
                }
                if (v1) {
                    __nv_bfloat162 h = *(__nv_bfloat162*)(sdyn + XFHI + ((r1 * WST + c) << 1));
                    __nv_bfloat162 l = *(__nv_bfloat162*)(sdyn + XFLO + ((r1 * WST + c) << 1));
                    float x0 = __bfloat162float(h.x) + __bfloat162float(l.x);
                    float x1 = __bfloat162float(h.y) + __bfloat162float(l.y);
                    v10 = __expf(x0) * i0 * fmaxf(acc[q][2], 0.f);
                    v11 = __expf(x1) * i1 * fmaxf(acc[q][3], 0.f);
                }
                const int kst = nt >> 1;
                const int h2  = (nt & 1) * 2;
                axh[mt][kst][0 + h2] = pack_bf2(v00, v01);
                axh[mt][kst][1 + h2] = pack_bf2(v10, v11);
            }
        }
    }

    // ---- stage B: four 64-col quarters of Wo1; B frags shared by 2 m-tiles ----
    float rs[2][2];
    rs[0][0] = rs[0][1] = rs[1][0] = rs[1][1] = 0.f;
    const uint32_t bPr264 = sbase +
        (((((lane & 7) + ((lane >> 4) << 3)) * 264) + ((lane >> 3) & 1) * 8) << 1);

    #pragma unroll
    for (int q4 = 0; q4 < 4; q4++) {
        __syncthreads();   // prior reads of the quarter region (or WE) complete
        copy_wo1_quarter(sdyn, WQHI, 0, q4, t, bany != 0);
        copy_wo1_quarter(sdyn, WQLO, 1, q4, t, bany != 0);
        __syncthreads();

        #pragma unroll
        for (int ntg = 0; ntg < 8; ntg += 4) {
            float acc[2][4][4];
            #pragma unroll
            for (int mt = 0; mt < 2; mt++)
                #pragma unroll
                for (int q = 0; q < 4; q++)
                    acc[mt][q][0] = acc[mt][q][1] = acc[mt][q][2] = acc[mt][q][3] = 0.f;
            #pragma unroll
            for (int ks = 0; ks < 8; ks++) {
                uint32_t ah0[4], al0[4], ah1[4], al1[4];
                ldsm_x4(aAddr0 + ks * 32, ah0);
                ldsm_x4(aAddr0 + (XFLO - XFHI) + ks * 32, al0);
                ldsm_x4(aAddr1 + ks * 32, ah1);
                ldsm_x4(aAddr1 + (XFLO - XFHI) + ks * 32, al1);
                // xf part (bf16x3): Wo1 rows k = 128 + ks*16
                {
                    uint32_t bhA[4], bhB[4], blA[4], blB[4];
                    const uint32_t ko = (128 + ks * 16) * 2;
                    ldsm_x4(bPr264 + WQHI + (ntg + 0) * (8 * 264 * 2) + ko, bhA);
                    ldsm_x4(bPr264 + WQHI + (ntg + 2) * (8 * 264 * 2) + ko, bhB);
                    ldsm_x4(bPr264 + WQLO + (ntg + 0) * (8 * 264 * 2) + ko, blA);
                    ldsm_x4(bPr264 + WQLO + (ntg + 2) * (8 * 264 * 2) + ko, blB);
                    mma16816(acc[0][0], ah0, bhA);  mma16816(acc[0][1], ah0, bhA + 2);
                    mma16816(acc[0][2], ah0, bhB);  mma16816(acc[0][3], ah0, bhB + 2);
                    mma16816(acc[1][0], ah1, bhA);  mma16816(acc[1][1], ah1, bhA + 2);
                    mma16816(acc[1][2], ah1, bhB);  mma16816(acc[1][3], ah1, bhB + 2);
                    mma16816(acc[0][0], ah0, blA);  mma16816(acc[0][1], ah0, blA + 2);
                    mma16816(acc[0][2], ah0, blB);  mma16816(acc[0][3], ah0, blB + 2);
                    mma16816(acc[1][0], ah1, blA);  mma16816(acc[1][1], ah1, blA + 2);
                    mma16816(acc[1][2], ah1, blB);  mma16816(acc[1][3], ah1, blB + 2);
                    mma16816(acc[0][0], al0, bhA);  mma16816(acc[0][1], al0, bhA + 2);
                    mma16816(acc[0][2], al0, bhB);  mma16816(acc[0][3], al0, bhB + 2);
                    mma16816(acc[1][0], al1, bhA);  mma16816(acc[1][1], al1, bhA + 2);
                    mma16816(acc[1][2], al1, bhB);  mma16816(acc[1][3], al1, bhB + 2);
                }
                // axi part (plain bf16): Wo1 rows k = ks*16, gated per m-group
                if (anyv0 || anyv1) {
                    uint32_t bhA[4], bhB[4];
                    const uint32_t ko = (ks * 16) * 2;
                    ldsm_x4(bPr264 + WQHI + (ntg + 0) * (8 * 264 * 2) + ko, bhA);
                    ldsm_x4(bPr264 + WQHI + (ntg + 2) * (8 * 264 * 2) + ko, bhB);
                    if (anyv0) {
                        mma16816(acc[0][0], axh[0][ks], bhA);  mma16816(acc[0][1], axh[0][ks], bhA + 2);
                        mma16816(acc[0][2], axh[0][ks], bhB);  mma16816(acc[0][3], axh[0][ks], bhB + 2);
                    }
                    if (anyv1) {
                        mma16816(acc[1][0], axh[1][ks], bhA);  mma16816(acc[1][1], axh[1][ks], bhA + 2);
                        mma16816(acc[1][2], axh[1][ks], bhB);  mma16816(acc[1][3], axh[1][ks], bhB + 2);
                    }
                }
            }
            #pragma unroll
            for (int mt = 0; mt < 2; mt++)
                #pragma unroll
                for (int q = 0; q < 4; q++) {
                    const int col = q4 * 64 + (ntg + q) * 8 + c2;
                    const float g0 = fmaxf(acc[mt][q][0] + s_bo1[col],     0.f);
                    const float g1 = fmaxf(acc[mt][q][1] + s_bo1[col + 1], 0.f);
                    const float g2 = fmaxf(acc[mt][q][2] + s_bo1[col],     0.f);
                    const float g3 = fmaxf(acc[mt][q][3] + s_bo1[col + 1], 0.f);
                    rs[mt][0] += g0 * s_wo2[col] + g1 * s_wo2[col + 1];
                    rs[mt][1] += g2 * s_wo2[col] + g3 * s_wo2[col + 1];
                }
        }
    }

    #pragma unroll
    for (int mt = 0; mt < 2; mt++) {
        rs[mt][0] += __shfl_xor_sync(0xffffffffu, rs[mt][0], 1);
        rs[mt][0] += __shfl_xor_sync(0xffffffffu, rs[mt][0], 2);
        rs[mt][1] += __shfl_xor_sync(0xffffffffu, rs[mt][1], 1);
        rs[mt][1] += __shfl_xor_sync(0xffffffffu, rs[mt][1], 2);
    }
    if ((lane & 3) == 0) {
        const float b2 = bo2[0];
        #pragma unroll
        for (int mt = 0; mt < 2; mt++) {
            out[row0 + mt * 128 + w * 16 + g]     = rs[mt][0] + b2;
            out[row0 + mt * 128 + w * 16 + g + 8] = rs[mt][1] + b2;
        }
    }
}

// ---------------------------------------------------------------------------
extern "C" void kernel_launch(void* const* d_in, const int* in_sizes, int n_in,
                              void* d_out, int out_size) {
    const float* x          = (const float*)d_in[0];
    const unsigned char* mk = (const unsigned char*)d_in[1];
    const float* Wi1        = (const float*)d_in[2];
    const float* bi1        = (const float*)d_in[3];
    const float* Wi2        = (const float*)d_in[4];
    const float* bi2        = (const float*)d_in[5];
    const float* We         = (const float*)d_in[6];
    const float* Wo1        = (const float*)d_in[7];
    const float* bo1        = (const float*)d_in[8];
    const float* Wo2        = (const float*)d_in[9];
    const float* bo2        = (const float*)d_in[10];
    float* out              = (float*)d_out;

    cudaFuncSetAttribute(k_embed_hmma, cudaFuncAttributeMaxDynamicSharedMemorySize, DSMEM);
    cudaFuncSetAttribute(k_out_hmma, cudaFuncAttributeMaxDynamicSharedMemorySize, DSMEM_OUT);

    const int prep_elems = 6 * 128 * WST + 2 * 65536;
    k_setup<<<1, 512>>>(mk);
    k_prep<<<(prep_elems + 255) / 256, 256>>>(Wi1, Wi2, We, Wo1);
    k_embed_hmma<<<RT / 256, 256, DSMEM>>>(x, bi1, bi2);
    k_out_hmma<<<RT / 256, 256, DSMEM_OUT>>>(bo1, Wo2, bo2, out);
}

// round 15
// speedup vs baseline: 1.4076x; 1.4076x over previous
#include <cuda_runtime.h>
#include <cuda_bf16.h>
#include <cstdint>

#define B_   4
#define N_   40
#define NC   64000      // 40^3
#define RT   256000     // B * N^3
#define WST  136

typedef unsigned long long u64;

// ---------------- scratch (device globals per allocation rules) ------------
__device__ float g_xembed[(size_t)RT * 128];
__device__ float g_sumexp[B_ * 128];
__device__ int   g_len[B_];
__device__ __align__(16) unsigned short g_wT[4][128 * WST];     // Wi1/Wi2 hi,lo [n][k]
__device__ __align__(16) unsigned short g_weT[2][128 * WST];    // We hi,lo [n][k]
__device__ __align__(16) unsigned short g_wo1T[2][256 * 256];   // Wo1 hi,lo [n][k]

// ---------------- helpers ---------------------------------------------------
static __device__ __forceinline__ uint32_t smem_u32(const void* p) {
    uint32_t a;
    asm("{ .reg .u64 t; cvta.to.shared.u64 t, %1; cvt.u32.u64 %0, t; }" : "=r"(a) : "l"(p));
    return a;
}
static __device__ __forceinline__ float bfhi(float f) {
    return __bfloat162float(__float2bfloat16(f));
}
static __device__ __forceinline__ uint32_t pack_bf2(float lo, float hi) {
    __nv_bfloat162 h = __floats2bfloat162_rn(lo, hi);
    return *reinterpret_cast<uint32_t*>(&h);
}
static __device__ __forceinline__ void ldsm_x4(uint32_t a, uint32_t* r) {
    asm volatile("ldmatrix.sync.aligned.m8n8.x4.shared.b16 {%0,%1,%2,%3}, [%4];"
        : "=r"(r[0]), "=r"(r[1]), "=r"(r[2]), "=r"(r[3]) : "r"(a));
}
static __device__ __forceinline__ void mma16816(float* d, const uint32_t* a, const uint32_t* b) {
    asm volatile("mma.sync.aligned.m16n8k16.row.col.f32.bf16.bf16.f32 "
        "{%0,%1,%2,%3}, {%4,%5,%6,%7}, {%8,%9}, {%0,%1,%2,%3};"
        : "+f"(d[0]), "+f"(d[1]), "+f"(d[2]), "+f"(d[3])
        : "r"(a[0]), "r"(a[1]), "r"(a[2]), "r"(a[3]), "r"(b[0]), "r"(b[1]));
}

// ---------------------------------------------------------------------------
// Kernel 0a: mask -> lengths, zero softmax denominators.
// ---------------------------------------------------------------------------
__global__ void k_setup(const unsigned char* __restrict__ mraw) {
    int t = threadIdx.x;
    if (t < B_ * 128) g_sumexp[t] = 0.f;
    if (t < B_) {
        int cnt = 0;
        if (mraw[1] != 0) {
            for (int j = 0; j < N_; j++) cnt += (mraw[t * N_ + j] != 0) ? 1 : 0;
        } else {
            const unsigned int* mi = (const unsigned int*)mraw;
            for (int j = 0; j < N_; j++) cnt += (mi[t * N_ + j] != 0u) ? 1 : 0;
        }
        g_len[t] = cnt;
    }
}

// ---------------------------------------------------------------------------
// Kernel 0b: transposed bf16 hi/lo weight images for Wi1, Wi2, We, Wo1.
// ---------------------------------------------------------------------------
__global__ void k_prep(const float* __restrict__ Wi1, const float* __restrict__ Wi2,
                       const float* __restrict__ We,  const float* __restrict__ Wo1) {
    int idx = blockIdx.x * 256 + threadIdx.x;
    if (idx < 4 * 128 * WST) {
        int mat = idx / (128 * WST);
        int r   = idx % (128 * WST);
        int n   = r / WST;
        int k   = r % WST;
        float v = 0.f;
        if (k < 128) {
            v = (mat < 2 ? Wi1 : Wi2)[k * 128 + n];
            if (mat & 1) v = v - bfhi(v);
        }
        __nv_bfloat16 h = __float2bfloat16(v);
        g_wT[mat][n * WST + k] = *reinterpret_cast<unsigned short*>(&h);
    } else if (idx < 6 * 128 * WST) {
        int r   = idx - 4 * 128 * WST;
        int img = r / (128 * WST);
        int rr  = r % (128 * WST);
        int n   = rr / WST;
        int k   = rr % WST;
        float v = 0.f;
        if (k < 128) {
            v = We[k * 128 + n];
            if (img) v = v - bfhi(v);
        }
        __nv_bfloat16 h = __float2bfloat16(v);
        g_weT[img][n * WST + k] = *reinterpret_cast<unsigned short*>(&h);
    } else if (idx < 6 * 128 * WST + 2 * 65536) {
        int r   = idx - 6 * 128 * WST;
        int img = r / 65536;
        int rr  = r % 65536;
        int n   = rr / 256;
        int k   = rr % 256;
        float v = Wo1[k * 256 + n];
        if (img) v = v - bfhi(v);
        __nv_bfloat16 h = __float2bfloat16(v);
        g_wo1T[img][n * 256 + k] = *reinterpret_cast<unsigned short*>(&h);
    }
}

// ---------------------------------------------------------------------------
// Kernel 1 (HMMA, round-8/13 best): x_embed + sumexp. 128 rows per CTA.
// ---------------------------------------------------------------------------
#define AHI_OFF 0
#define ALO_OFF 34816
#define W_OFF   69632
#define WIMG    34816
#define SXF_STRIDE 132
#define DSMEM   208896

extern __shared__ unsigned char sdyn[];
__global__ __launch_bounds__(256, 1) void k_embed_hmma(
    const float* __restrict__ x,
    const float* __restrict__ bi1, const float* __restrict__ bi2)
{
    __shared__ float s_bias1[128], s_bias2[128];
    __shared__ unsigned char s_vf[128];

    const int t    = threadIdx.x;
    const int lane = t & 31;
    const int w    = t >> 5;
    const int row0 = blockIdx.x * 128;
    const int b    = row0 / NC;
    const uint32_t sbase = smem_u32(sdyn);

    {
        const float4* ws = (const float4*)g_wT;
        float4* wd = (float4*)(sdyn + W_OFF);
        #pragma unroll
        for (int i = 0; i < 34; i++) wd[t + i * 256] = ws[t + i * 256];
    }
    {
        const float4* xg = (const float4*)(x + (size_t)row0 * 128);
        #pragma unroll
        for (int i = 0; i < 16; i++) {
            int fidx = t + i * 256;
            float4 v = xg[fidx];
            int row = fidx >> 5;
            int k   = (fidx & 31) * 4;
            uint32_t hA = pack_bf2(v.x, v.y);
            uint32_t hB = pack_bf2(v.z, v.w);
            uint32_t lA = pack_bf2(v.x - bfhi(v.x), v.y - bfhi(v.y));
            uint32_t lB = pack_bf2(v.z - bfhi(v.z), v.w - bfhi(v.w));
            size_t off = ((size_t)row * WST + k) * 2;
            *(u64*)(sdyn + AHI_OFF + off) = ((u64)hB << 32) | hA;
            *(u64*)(sdyn + ALO_OFF + off) = ((u64)lB << 32) | lA;
        }
    }
    if (t < 128) {
        s_bias1[t] = bi1[t];
        s_bias2[t] = bi2[t];
        const int lenb = g_len[b];
        const int rem = row0 + t - b * NC;
        const int i  = rem / 1600;
        const int j  = (rem / 40) % 40;
        const int kk = rem % 40;
        s_vf[t] = (i < j) && (j < kk) && (kk < lenb);
    }
    __syncthreads();

    const int m0 = w * 16;
    const int c2 = (lane & 3) * 2;
    const uint32_t aHi = sbase + AHI_OFF + (((m0 + (lane & 15)) * WST + (lane >> 4) * 8) << 1);
    const uint32_t aLo = aHi + (ALO_OFF - AHI_OFF);
    const uint32_t bPr = sbase + W_OFF +
        (((((lane & 7) + ((lane >> 4) << 3)) * WST) + ((lane >> 3) & 1) * 8) << 1);

    float acc[16][4];
    #pragma unroll
    for (int nt = 0; nt < 16; nt++)
        acc[nt][0] = acc[nt][1] = acc[nt][2] = acc[nt][3] = 0.f;

    #pragma unroll
    for (int ks = 0; ks < 8; ks++) {
        uint32_t ahi[4], alo[4];
        ldsm_x4(aHi + ks * 32, ahi);
        ldsm_x4(aLo + ks * 32, alo);
        #pragma unroll
        for (int nt = 0; nt < 16; nt += 2) {
            uint32_t bh[4], bl[4];
            ldsm_x4(bPr + 0 * WIMG + nt * (8 * WST * 2) + ks * 32, bh);
            ldsm_x4(bPr + 1 * WIMG + nt * (8 * WST * 2) + ks * 32, bl);
            mma16816(acc[nt], ahi, bh);     mma16816(acc[nt + 1], ahi, bh + 2);
            mma16816(acc[nt], ahi, bl);     mma16816(acc[nt + 1], ahi, bl + 2);
            mma16816(acc[nt], alo, bh);     mma16816(acc[nt + 1], alo, bh + 2);
        }
    }
    __syncthreads();

    uint32_t a2h[8][4], a2l[8][4];
    #pragma unroll
    for (int ks = 0; ks < 8; ks++) {
        #pragma unroll
        for (int h = 0; h < 2; h++) {
            const int nt = 2 * ks + h;
            const float b0 = s_bias1[nt * 8 + c2];
            const float b1 = s_bias1[nt * 8 + c2 + 1];
            float f0 = fmaxf(acc[nt][0] + b0, 0.f);
            float f1 = fmaxf(acc[nt][1] + b1, 0.f);
            float f2 = fmaxf(acc[nt][2] + b0, 0.f);
            float f3 = fmaxf(acc[nt][3] + b1, 0.f);
            a2h[ks][0 + 2 * h] = pack_bf2(f0, f1);
            a2h[ks][1 + 2 * h] = pack_bf2(f2, f3);
            a2l[ks][0 + 2 * h] = pack_bf2(f0 - bfhi(f0), f1 - bfhi(f1));
            a2l[ks][1 + 2 * h] = pack_bf2(f2 - bfhi(f2), f3 - bfhi(f3));
        }
    }

    #pragma unroll
    for (int nt = 0; nt < 16; nt++)
        acc[nt][0] = acc[nt][1] = acc[nt][2] = acc[nt][3] = 0.f;
    #pragma unroll
    for (int ks = 0; ks < 8; ks++) {
        #pragma unroll
        for (int nt = 0; nt < 16; nt += 2) {
            uint32_t bh[4], bl[4];
            ldsm_x4(bPr + 2 * WIMG + nt * (8 * WST * 2) + ks * 32, bh);
            ldsm_x4(bPr + 3 * WIMG + nt * (8 * WST * 2) + ks * 32, bl);
            mma16816(acc[nt], a2h[ks], bh); mma16816(acc[nt + 1], a2h[ks], bh + 2);
            mma16816(acc[nt], a2h[ks], bl); mma16816(acc[nt + 1], a2h[ks], bl + 2);
            mma16816(acc[nt], a2l[ks], bh); mma16816(acc[nt + 1], a2l[ks], bh + 2);
        }
    }

    float* sxf = (float*)sdyn;
    const int g = lane >> 2;
    #pragma unroll
    for (int nt = 0; nt < 16; nt++) {
        const int nc = nt * 8 + c2;
        const float b0 = s_bias2[nc], b1 = s_bias2[nc + 1];
        *(float2*)(&sxf[(m0 + g) * SXF_STRIDE + nc])     = make_float2(acc[nt][0] + b0, acc[nt][1] + b1);
        *(float2*)(&sxf[(m0 + g + 8) * SXF_STRIDE + nc]) = make_float2(acc[nt][2] + b0, acc[nt][3] + b1);
    }
    __syncthreads();

    {
        float4* xo = (float4*)(g_xembed + (size_t)row0 * 128);
        #pragma unroll
        for (int i = 0; i < 16; i++) {
            int idx = t + i * 256;
            int row = idx >> 5;
            int c4  = (idx & 31) * 4;
            const float* p = &sxf[row * SXF_STRIDE + c4];
            xo[idx] = make_float4(p[0], p[1], p[2], p[3]);
        }
    }
    if (t < 128) {
        float s = 0.f;
        for (int r = 0; r < 128; r++)
            if (s_vf[r]) s += __expf(sxf[r * SXF_STRIDE + t]);
        if (s != 0.f) atomicAdd(&g_sumexp[b * 128 + t], s);
    }
}

// ---------------------------------------------------------------------------
// Kernel 2 (HMMA v4, R13 base): 256 rows per CTA, warp = M32 (two m-tiles).
// Wo1 staged in 64-col quarters; B frags shared by both m-tiles. Stage A:
// parallel m-tiles, ntg step 2 (acc[2][2][4]) for register relief.
// ---------------------------------------------------------------------------
#define XFHI 0
#define XFLO 69632
#define WEHI 139264
#define WQHI 139264
#define WQLO 173056
#define DSMEM_OUT 206848

// copy one 64-col Wo1 quarter image into a 264-stride smem buffer.
static __device__ __forceinline__ void copy_wo1_quarter(
    unsigned char* sm, uint32_t dst0, int img, int q, int t, bool full)
{
    const uint4* src = (const uint4*)(g_wo1T[img] + (size_t)(q * 64) * 256);
    if (full) {
        #pragma unroll
        for (int i = 0; i < 8; i++) {
            int e = t + i * 256;
            int r = e >> 5;
            int kq = (e & 31) * 8;
            *(uint4*)(sm + dst0 + ((r * 264 + kq) << 1)) = src[e];
        }
    } else {
        #pragma unroll
        for (int i = 0; i < 4; i++) {
            int e = t + i * 256;
            int r = e >> 4;
            int kq = 128 + (e & 15) * 8;
            *(uint4*)(sm + dst0 + ((r * 264 + kq) << 1)) = src[r * 32 + (kq >> 3)];
        }
    }
}

__global__ __launch_bounds__(256, 1) void k_out_hmma(
    const float* __restrict__ bo1,
    const float* __restrict__ Wo2, const float* __restrict__ bo2,
    float* __restrict__ out)
{
    __shared__ float s_bo1[256], s_wo2[256], s_inv[128];
    __shared__ unsigned char s_vf[256];

    const int t    = threadIdx.x;
    const int lane = t & 31;
    const int w    = t >> 5;
    const int row0 = blockIdx.x * 256;   // 64000 % 256 == 0: no batch straddle
    const int b    = row0 / NC;
    const uint32_t sbase = smem_u32(sdyn);

    if (t < 128) s_inv[t] = 1.0f / g_sumexp[b * 128 + t];
    {
        const int lenb = g_len[b];
        const int rem = row0 + t - b * NC;
        const int i  = rem / 1600;
        const int j  = (rem / 40) % 40;
        const int kk = rem % 40;
        s_vf[t] = (i < j) && (j < kk) && (kk < lenb);
    }
    s_bo1[t] = bo1[t];
    s_wo2[t] = Wo2[t];
    const int bany = __syncthreads_or((int)s_vf[t]);

    // xf tiles (256 rows) -> bf16 hi/lo images
    {
        const float4* xg = (const float4*)(g_xembed + (size_t)row0 * 128);
        #pragma unroll
        for (int i = 0; i < 32; i++) {
            int fidx = t + i * 256;
            float4 v = xg[fidx];
            int row = fidx >> 5;
            int k   = (fidx & 31) * 4;
            uint32_t hA = pack_bf2(v.x, v.y);
            uint32_t hB = pack_bf2(v.z, v.w);
            uint32_t lA = pack_bf2(v.x - bfhi(v.x), v.y - bfhi(v.y));
            uint32_t lB = pack_bf2(v.z - bfhi(v.z), v.w - bfhi(v.w));
            size_t off = ((size_t)row * WST + k) * 2;
            *(u64*)(sdyn + XFHI + off) = ((u64)hB << 32) | hA;
            *(u64*)(sdyn + XFLO + off) = ((u64)lB << 32) | lA;
        }
    }
    // We hi image (stage A plain bf16) — only when CTA has valid rows
    if (bany) {
        const float4* ws = (const float4*)g_weT[0];
        float4* wd = (float4*)(sdyn + WEHI);
        #pragma unroll
        for (int i = 0; i < 9; i++) {
            int e = t + i * 256;
            if (e < 2176) wd[e] = ws[e];
        }
    }
    __syncthreads();

    const int c2 = (lane & 3) * 2;
    const int g  = lane >> 2;
    const uint32_t aAddr0 = sbase + XFHI + (((w * 16 + (lane & 15)) * WST + (lane >> 4) * 8) << 1);
    const uint32_t aAddr1 = aAddr0 + (128 * WST * 2);
    const uint32_t bPr136 = sbase +
        (((((lane & 7) + ((lane >> 4) << 3)) * WST) + ((lane >> 3) & 1) * 8) << 1);

    const int anyv0 = __any_sync(0xffffffffu, (int)s_vf[w * 16 + (lane & 15)]);
    const int anyv1 = __any_sync(0xffffffffu, (int)s_vf[128 + w * 16 + (lane & 15)]);

    // ---- stage A (plain bf16): axi = a .* relu(xf @ We); frags in registers ----
    uint32_t axh[2][8][4];
    if (anyv0 || anyv1) {
        #pragma unroll
        for (int ntg = 0; ntg < 16; ntg += 2) {
            float acc[2][2][4];
            #pragma unroll
            for (int mt = 0; mt < 2; mt++)
                #pragma unroll
                for (int q = 0; q < 2; q++)
                    acc[mt][q][0] = acc[mt][q][1] = acc[mt][q][2] = acc[mt][q][3] = 0.f;
            #pragma unroll
            for (int ks = 0; ks < 8; ks++) {
                uint32_t bhA[4];
                ldsm_x4(bPr136 + WEHI + ntg * (8 * WST * 2) + ks * 32, bhA);
                if (anyv0) {
                    uint32_t ah[4];
                    ldsm_x4(aAddr0 + ks * 32, ah);
                    mma16816(acc[0][0], ah, bhA);  mma16816(acc[0][1], ah, bhA + 2);
                }
                if (anyv1) {
                    uint32_t ah[4];
                    ldsm_x4(aAddr1 + ks * 32, ah);
                    mma16816(acc[1][0], ah, bhA);  mma16816(acc[1][1], ah, bhA + 2);
                }
            }
            // epilogue -> bf16 A-fragments for cols [ntg*8, ntg*8+16)
            #pragma unroll
            for (int mt = 0; mt < 2; mt++) {
                if (!(mt == 0 ? anyv0 : anyv1)) continue;
                const int r0 = mt * 128 + w * 16 + g, r1 = r0 + 8;
                const bool v0 = s_vf[r0], v1 = s_vf[r1];
                #pragma unroll
                for (int q = 0; q < 2; q++) {
                    const int nt = ntg + q;
                    const int c = nt * 8 + c2;
                    const float i0 = s_inv[c], i1 = s_inv[c + 1];
                    float v00 = 0.f, v01 = 0.f, v10 = 0.f, v11 = 0.f;
                    if (v0) {
                        __nv_bfloat162 h = *(__nv_bfloat162*)(sdyn + XFHI + ((r0 * WST + c) << 1));
                        __nv_bfloat162 l = *(__nv_bfloat162*)(sdyn + XFLO + ((r0 * WST + c) << 1));
                        float x0 = __bfloat162float(h.x) + __bfloat162float(l.x);
                        float x1 = __bfloat162float(h.y) + __bfloat162float(l.y);
                        v00 = __expf(x0) * i0 * fmaxf(acc[mt][q][0], 0.f);
                        v01 = __expf(x1) * i1 * fmaxf(acc[mt][q][1], 0.f);
                    }
                    if (v1) {
                        __nv_bfloat162 h = *(__nv_bfloat162*)(sdyn + XFHI + ((r1 * WST + c) << 1));
                        __nv_bfloat162 l = *(__nv_bfloat162*)(sdyn + XFLO + ((r1 * WST + c) << 1));
                        float x0 = __bfloat162float(h.x) + __bfloat162float(l.x);
                        float x1 = __bfloat162float(h.y) + __bfloat162float(l.y);
                        v10 = __expf(x0) * i0 * fmaxf(acc[mt][q][2], 0.f);
                        v11 = __expf(x1) * i1 * fmaxf(acc[mt][q][3], 0.f);
                    }
                    const int kst = nt >> 1;
                    const int h2  = (nt & 1) * 2;
                    axh[mt][kst][0 + h2] = pack_bf2(v00, v01);
                    axh[mt][kst][1 + h2] = pack_bf2(v10, v11);
                }
            }
        }
    }

    // ---- stage B: four 64-col quarters of Wo1; B frags shared by 2 m-tiles ----
    float rs[2][2];
    rs[0][0] = rs[0][1] = rs[1][0] = rs[1][1] = 0.f;
    const uint32_t bPr264 = sbase +
        (((((lane & 7) + ((lane >> 4) << 3)) * 264) + ((lane >> 3) & 1) * 8) << 1);

    #pragma unroll
    for (int q4 = 0; q4 < 4; q4++) {
        __syncthreads();   // prior reads of the quarter region (or WE) complete
        copy_wo1_quarter(sdyn, WQHI, 0, q4, t, bany != 0);
        copy_wo1_quarter(sdyn, WQLO, 1, q4, t, bany != 0);
        __syncthreads();

        #pragma unroll
        for (int ntg = 0; ntg < 8; ntg += 4) {
            float acc[2][4][4];
            #pragma unroll
            for (int mt = 0; mt < 2; mt++)
                #pragma unroll
                for (int q = 0; q < 4; q++)
                    acc[mt][q][0] = acc[mt][q][1] = acc[mt][q][2] = acc[mt][q][3] = 0.f;
            #pragma unroll
            for (int ks = 0; ks < 8; ks++) {
                uint32_t ah0[4], al0[4], ah1[4], al1[4];
                ldsm_x4(aAddr0 + ks * 32, ah0);
                ldsm_x4(aAddr0 + (XFLO - XFHI) + ks * 32, al0);
                ldsm_x4(aAddr1 + ks * 32, ah1);
                ldsm_x4(aAddr1 + (XFLO - XFHI) + ks * 32, al1);
                // xf part (bf16x3): Wo1 rows k = 128 + ks*16
                {
                    uint32_t bhA[4], bhB[4], blA[4], blB[4];
                    const uint32_t ko = (128 + ks * 16) * 2;
                    ldsm_x4(bPr264 + WQHI + (ntg + 0) * (8 * 264 * 2) + ko, bhA);
                    ldsm_x4(bPr264 + WQHI + (ntg + 2) * (8 * 264 * 2) + ko, bhB);
                    ldsm_x4(bPr264 + WQLO + (ntg + 0) * (8 * 264 * 2) + ko, blA);
                    ldsm_x4(bPr264 + WQLO + (ntg + 2) * (8 * 264 * 2) + ko, blB);
                    mma16816(acc[0][0], ah0, bhA);  mma16816(acc[0][1], ah0, bhA + 2);
                    mma16816(acc[0][2], ah0, bhB);  mma16816(acc[0][3], ah0, bhB + 2);
                    mma16816(acc[1][0], ah1, bhA);  mma16816(acc[1][1], ah1, bhA + 2);
                    mma16816(acc[1][2], ah1, bhB);  mma16816(acc[1][3], ah1, bhB + 2);
                    mma16816(acc[0][0], ah0, blA);  mma16816(acc[0][1], ah0, blA + 2);
                    mma16816(acc[0][2], ah0, blB);  mma16816(acc[0][3], ah0, blB + 2);
                    mma16816(acc[1][0], ah1, blA);  mma16816(acc[1][1], ah1, blA + 2);
                    mma16816(acc[1][2], ah1, blB);  mma16816(acc[1][3], ah1, blB + 2);
                    mma16816(acc[0][0], al0, bhA);  mma16816(acc[0][1], al0, bhA + 2);
                    mma16816(acc[0][2], al0, bhB);  mma16816(acc[0][3], al0, bhB + 2);
                    mma16816(acc[1][0], al1, bhA);  mma16816(acc[1][1], al1, bhA + 2);
                    mma16816(acc[1][2], al1, bhB);  mma16816(acc[1][3], al1, bhB + 2);
                }
                // axi part (plain bf16): Wo1 rows k = ks*16, gated per m-group
                if (anyv0 || anyv1) {
                    uint32_t bhA[4], bhB[4];
                    const uint32_t ko = (ks * 16) * 2;
                    ldsm_x4(bPr264 + WQHI + (ntg + 0) * (8 * 264 * 2) + ko, bhA);
                    ldsm_x4(bPr264 + WQHI + (ntg + 2) * (8 * 264 * 2) + ko, bhB);
                    if (anyv0) {
                        mma16816(acc[0][0], axh[0][ks], bhA);  mma16816(acc[0][1], axh[0][ks], bhA + 2);
                        mma16816(acc[0][2], axh[0][ks], bhB);  mma16816(acc[0][3], axh[0][ks], bhB + 2);
                    }
                    if (anyv1) {
                        mma16816(acc[1][0], axh[1][ks], bhA);  mma16816(acc[1][1], axh[1][ks], bhA + 2);
                        mma16816(acc[1][2], axh[1][ks], bhB);  mma16816(acc[1][3], axh[1][ks], bhB + 2);
                    }
                }
            }
            #pragma unroll
            for (int mt = 0; mt < 2; mt++)
                #pragma unroll
                for (int q = 0; q < 4; q++) {
                    const int col = q4 * 64 + (ntg + q) * 8 + c2;
                    const float g0 = fmaxf(acc[mt][q][0] + s_bo1[col],     0.f);
                    const float g1 = fmaxf(acc[mt][q][1] + s_bo1[col + 1], 0.f);
                    const float g2 = fmaxf(acc[mt][q][2] + s_bo1[col],     0.f);
                    const float g3 = fmaxf(acc[mt][q][3] + s_bo1[col + 1], 0.f);
                    rs[mt][0] += g0 * s_wo2[col] + g1 * s_wo2[col + 1];
                    rs[mt][1] += g2 * s_wo2[col] + g3 * s_wo2[col + 1];
                }
        }
    }

    #pragma unroll
    for (int mt = 0; mt < 2; mt++) {
        rs[mt][0] += __shfl_xor_sync(0xffffffffu, rs[mt][0], 1);
        rs[mt][0] += __shfl_xor_sync(0xffffffffu, rs[mt][0], 2);
        rs[mt][1] += __shfl_xor_sync(0xffffffffu, rs[mt][1], 1);
        rs[mt][1] += __shfl_xor_sync(0xffffffffu, rs[mt][1], 2);
    }
    if ((lane & 3) == 0) {
        const float b2 = bo2[0];
        #pragma unroll
        for (int mt = 0; mt < 2; mt++) {
            out[row0 + mt * 128 + w * 16 + g]     = rs[mt][0] + b2;
            out[row0 + mt * 128 + w * 16 + g + 8] = rs[mt][1] + b2;
        }
    }
}

// ---------------------------------------------------------------------------
extern "C" void kernel_launch(void* const* d_in, const int* in_sizes, int n_in,
                              void* d_out, int out_size) {
    const float* x          = (const float*)d_in[0];
    const unsigned char* mk = (const unsigned char*)d_in[1];
    const float* Wi1        = (const float*)d_in[2];
    const float* bi1        = (const float*)d_in[3];
    const float* Wi2        = (const float*)d_in[4];
    const float* bi2        = (const float*)d_in[5];
    const float* We         = (const float*)d_in[6];
    const float* Wo1        = (const float*)d_in[7];
    const float* bo1        = (const float*)d_in[8];
    const float* Wo2        = (const float*)d_in[9];
    const float* bo2        = (const float*)d_in[10];
    float* out              = (float*)d_out;

    cudaFuncSetAttribute(k_embed_hmma, cudaFuncAttributeMaxDynamicSharedMemorySize, DSMEM);
    cudaFuncSetAttribute(k_out_hmma, cudaFuncAttributeMaxDynamicSharedMemorySize, DSMEM_OUT);

    const int prep_elems = 6 * 128 * WST + 2 * 65536;
    k_setup<<<1, 512>>>(mk);
    k_prep<<<(prep_elems + 255) / 256, 256>>>(Wi1, Wi2, We, Wo1);
    k_embed_hmma<<<RT / 128, 256, DSMEM>>>(x, bi1, bi2);
    k_out_hmma<<<RT / 256, 256, DSMEM_OUT>>>(bo1, Wo2, bo2, out);
}